// round 6
// baseline (speedup 1.0000x reference)
#include <cuda_runtime.h>
#include <cuda_bf16.h>

#define NN 10000
#define NS 64
#define NV 64
#define HID 128
#define WN 320
#define KS0 192
#define EAD 20
#define TPS 128
#define TPV 192

#define TE 16
#define BT 320

#define INV_SQRT3 0.5773502691896258f
#define INV_SQRT2 0.7071067811865476f

// smem offsets (floats)
#define OFF_S0T   0        // [192][16]
#define OFF_H1T   3072     // [128][20] padded rows
#define OFF_R1T   5632     // [128][20]
#define OFF_VT    0        // [192][48] overlays s0t/h1t/r1t after ph3
#define OFF_SPS   9216     // [128][16]
#define OFF_VPS   11264    // [384][16]
#define OFF_TPW   17408    // [320][20] padded rows
#define OFF_OUTS  23808    // [128][16]
#define OFF_EAT   25856    // [20][16]
#define OFF_IDX   26176    // 32 ints
#define SMEM_FLOATS 26208

typedef unsigned long long u64;

__device__ float g_sp[NN * NS];
__device__ float g_vp[NN * 3 * NV];   // [n][c*64+v]

__device__ __forceinline__ float siluf(float x) { return x / (1.0f + __expf(-x)); }
__device__ __forceinline__ void fma2(u64& d, u64 a, u64 b) {
    asm("fma.rn.f32x2 %0, %1, %2, %0;" : "+l"(d) : "l"(a), "l"(b));
}
__device__ __forceinline__ u64 pk(float x, float y) {
    u64 r; asm("mov.b64 %0, {%1, %2};" : "=l"(r) : "f"(x), "f"(y)); return r;
}
__device__ __forceinline__ float2 up(u64 a) {
    float2 r; asm("mov.b64 {%0, %1}, %2;" : "=f"(r.x), "=f"(r.y) : "l"(a)); return r;
}

// ---------------------------------------------------------------------------
__global__ __launch_bounds__(256) void node_kernel(
    const float* __restrict__ x,
    const float* __restrict__ Wps, const float* __restrict__ bps,
    const float* __restrict__ Wpv,
    const float* __restrict__ gw, const float* __restrict__ gb,
    int N)
{
    __shared__ float sx[4][256];
    const int ln = threadIdx.x >> 6;
    const int v  = threadIdx.x & 63;
    const int n  = blockIdx.x * 4 + ln;

    if (n < N) {
        #pragma unroll
        for (int i = v; i < 256; i += 64) sx[ln][i] = x[n * 256 + i];
    }
    __syncthreads();
    if (n >= N) return;

    const float* xs = sx[ln];
    const float* xv = sx[ln] + 64;

    float sacc = bps[v];
    #pragma unroll 4
    for (int i = 0; i < NS; i++) sacc = fmaf(xs[i], Wps[i * NS + v], sacc);

    float ax = 0.f, ay = 0.f, az = 0.f;
    #pragma unroll 4
    for (int u = 0; u < NV; u++) {
        float w = Wpv[u * NV + v];
        ax = fmaf(xv[u * 3 + 0], w, ax);
        ay = fmaf(xv[u * 3 + 1], w, ay);
        az = fmaf(xv[u * 3 + 2], w, az);
    }
    float nrm = sqrtf(ax * ax + ay * ay + az * az + 1e-12f);
    float g = siluf(nrm * gw[v] + gb[v]);

    g_sp[n * NS + v] = siluf(sacc);
    g_vp[n * 192 + 0 * 64 + v] = ax * g;
    g_vp[n * 192 + 1 * 64 + v] = ay * g;
    g_vp[n * 192 + 2 * 64 + v] = az * g;
}

// ---------------------------------------------------------------------------
__global__ __launch_bounds__(BT, 2) void edge_kernel(
    const float* __restrict__ x,
    const float* __restrict__ edge_attr,
    const float* __restrict__ fij_in,
    const float* __restrict__ Ws1, const float* __restrict__ bs1,
    const float* __restrict__ Ws2, const float* __restrict__ bs2,
    const float* __restrict__ Wr1, const float* __restrict__ br1,
    const float* __restrict__ Wr2, const float* __restrict__ br2,
    const float* __restrict__ gwp, const float* __restrict__ gbp,
    const float* __restrict__ Wpost_s, const float* __restrict__ Wpost_v,
    const int* __restrict__ ei,
    float* __restrict__ out, int E)
{
    extern __shared__ float sm[];
    float* s0t   = sm + OFF_S0T;
    float* h1t   = sm + OFF_H1T;
    float* r1t   = sm + OFF_R1T;
    float* Vt    = sm + OFF_VT;
    float* spsT  = sm + OFF_SPS;
    float* vpsT  = sm + OFF_VPS;
    float* tpwT  = sm + OFF_TPW;
    float* outsT = sm + OFF_OUTS;
    float* eat   = sm + OFF_EAT;
    int*   sidx  = (int*)(sm + OFF_IDX);

    const int tid = threadIdx.x;
    const int e0  = blockIdx.x * TE;

    if (tid < 32) {
        int e = tid & 15;
        sidx[tid] = (tid < 16) ? ei[e0 + e] : ei[E + e0 + e];
    }
    __syncthreads();

    // ---- Phase 1 (tid<256): gather x, g_sp, g_vp; (tid>=256): load edge_attr ----
    if (tid < 256) {
        const int e = tid & 15, q = tid >> 4;
        const int s = sidx[e], d = sidx[TE + e];
        const float* xs = x + (size_t)s * 256;
        const float* xd = x + (size_t)d * 256;

        float4 a = *(const float4*)(xs + q * 4);
        float4 b = *(const float4*)(xd + q * 4);
        s0t[(q*4+0)*16+e] = a.x; s0t[(q*4+1)*16+e] = a.y;
        s0t[(q*4+2)*16+e] = a.z; s0t[(q*4+3)*16+e] = a.w;
        s0t[(64+q*4+0)*16+e] = b.x; s0t[(64+q*4+1)*16+e] = b.y;
        s0t[(64+q*4+2)*16+e] = b.z; s0t[(64+q*4+3)*16+e] = b.w;

        float4 v0 = *(const float4*)(xs + 64 + q*12);
        float4 v1 = *(const float4*)(xs + 64 + q*12 + 4);
        float4 v2 = *(const float4*)(xs + 64 + q*12 + 8);
        float4 w0 = *(const float4*)(xd + 64 + q*12);
        float4 w1 = *(const float4*)(xd + 64 + q*12 + 4);
        float4 w2 = *(const float4*)(xd + 64 + q*12 + 8);
        float d0 = v0.x*w0.x + v0.y*w0.y + v0.z*w0.z;
        float d1 = v0.w*w0.w + v1.x*w1.x + v1.y*w1.y;
        float d2 = v1.z*w1.z + v1.w*w1.w + v2.x*w2.x;
        float d3 = v2.y*w2.y + v2.z*w2.z + v2.w*w2.w;
        s0t[(128+q*4+0)*16+e] = d0; s0t[(128+q*4+1)*16+e] = d1;
        s0t[(128+q*4+2)*16+e] = d2; s0t[(128+q*4+3)*16+e] = d3;

        float4 gs = *(const float4*)(g_sp + (size_t)s * 64 + q * 4);
        float4 gd = *(const float4*)(g_sp + (size_t)d * 64 + q * 4);
        spsT[(q*4+0)*16+e] = gs.x; spsT[(q*4+1)*16+e] = gs.y;
        spsT[(q*4+2)*16+e] = gs.z; spsT[(q*4+3)*16+e] = gs.w;
        spsT[(64+q*4+0)*16+e] = gd.x; spsT[(64+q*4+1)*16+e] = gd.y;
        spsT[(64+q*4+2)*16+e] = gd.z; spsT[(64+q*4+3)*16+e] = gd.w;

        {
            float4 p0 = *(const float4*)(g_vp + (size_t)s * 192 + q * 12);
            float4 p1 = *(const float4*)(g_vp + (size_t)s * 192 + q * 12 + 4);
            float4 p2 = *(const float4*)(g_vp + (size_t)s * 192 + q * 12 + 8);
            float pv[12] = {p0.x,p0.y,p0.z,p0.w,p1.x,p1.y,p1.z,p1.w,p2.x,p2.y,p2.z,p2.w};
            #pragma unroll
            for (int r = 0; r < 12; r++) vpsT[(q*12 + r)*16 + e] = pv[r];
        }
        {
            float4 p0 = *(const float4*)(g_vp + (size_t)d * 192 + q * 12);
            float4 p1 = *(const float4*)(g_vp + (size_t)d * 192 + q * 12 + 4);
            float4 p2 = *(const float4*)(g_vp + (size_t)d * 192 + q * 12 + 8);
            float pv[12] = {p0.x,p0.y,p0.z,p0.w,p1.x,p1.y,p1.z,p1.w,p2.x,p2.y,p2.z,p2.w};
            #pragma unroll
            for (int r = 0; r < 12; r++) vpsT[(192 + q*12 + r)*16 + e] = pv[r];
        }
    } else {
        for (int idx = tid - 256; idx < TE * EAD; idx += 64) {
            eat[idx] = edge_attr[(size_t)(e0 + (idx & 15)) * EAD + (idx >> 4)];
        }
    }
    __syncthreads();

    // ---- Phase 2 (tid<256): thread = 2 k x 4 edges, both branches ----
    if (tid < 256) {
        const int kp = tid >> 2;   // k = kp*2, kp*2+1
        const int eq = tid & 3;    // edges eq*4..+3
        // s-branch (192 k-steps), chunk-4 ping-pong weight prefetch
        {
            const float* pw = Ws1 + kp*2;
            float2 bb = *(const float2*)(bs1 + kp*2);
            u64 a0[2] = {pk(bb.x,bb.x), pk(bb.x,bb.x)};
            u64 a1[2] = {pk(bb.y,bb.y), pk(bb.y,bb.y)};
            float2 wc[4];
            #pragma unroll
            for (int j = 0; j < 4; j++) wc[j] = *(const float2*)(pw + j*HID);
            for (int i = 0; i < KS0; i += 4) {
                float2 wn[4];
                const int inx = (i + 4 < KS0) ? i + 4 : i;   // clamped prefetch base
                #pragma unroll
                for (int j = 0; j < 4; j++) wn[j] = *(const float2*)(pw + (inx+j)*HID);
                #pragma unroll
                for (int j = 0; j < 4; j++) {
                    ulonglong2 aa = *(const ulonglong2*)(s0t + (i+j)*16 + eq*4);
                    u64 w0 = pk(wc[j].x, wc[j].x), w1 = pk(wc[j].y, wc[j].y);
                    fma2(a0[0], aa.x, w0); fma2(a0[1], aa.y, w0);
                    fma2(a1[0], aa.x, w1); fma2(a1[1], aa.y, w1);
                }
                #pragma unroll
                for (int j = 0; j < 4; j++) wc[j] = wn[j];
            }
            float2 q0 = up(a0[0]), q1 = up(a0[1]);
            *(u64*)(h1t + (kp*2)*20 + eq*4)     = pk(siluf(q0.x), siluf(q0.y));
            *(u64*)(h1t + (kp*2)*20 + eq*4 + 2) = pk(siluf(q1.x), siluf(q1.y));
            q0 = up(a1[0]); q1 = up(a1[1]);
            *(u64*)(h1t + (kp*2+1)*20 + eq*4)     = pk(siluf(q0.x), siluf(q0.y));
            *(u64*)(h1t + (kp*2+1)*20 + eq*4 + 2) = pk(siluf(q1.x), siluf(q1.y));
        }
        // r-branch (20 k-steps)
        {
            float2 bb = *(const float2*)(br1 + kp*2);
            u64 a0[2] = {pk(bb.x,bb.x), pk(bb.x,bb.x)};
            u64 a1[2] = {pk(bb.y,bb.y), pk(bb.y,bb.y)};
            #pragma unroll 4
            for (int i = 0; i < EAD; i++) {
                float2 w = *(const float2*)(Wr1 + i*HID + kp*2);
                ulonglong2 aa = *(const ulonglong2*)(eat + i*16 + eq*4);
                u64 w0 = pk(w.x,w.x), w1 = pk(w.y,w.y);
                fma2(a0[0], aa.x, w0); fma2(a0[1], aa.y, w0);
                fma2(a1[0], aa.x, w1); fma2(a1[1], aa.y, w1);
            }
            float2 q0 = up(a0[0]), q1 = up(a0[1]);
            *(u64*)(r1t + (kp*2)*20 + eq*4)     = pk(siluf(q0.x), siluf(q0.y));
            *(u64*)(r1t + (kp*2)*20 + eq*4 + 2) = pk(siluf(q1.x), siluf(q1.y));
            q0 = up(a1[0]); q1 = up(a1[1]);
            *(u64*)(r1t + (kp*2+1)*20 + eq*4)     = pk(siluf(q0.x), siluf(q0.y));
            *(u64*)(r1t + (kp*2+1)*20 + eq*4 + 2) = pk(siluf(q1.x), siluf(q1.y));
        }
    }
    __syncthreads();

    // ---- Phase 3: thread = 4 kv x 4 edges, chunk-2 ping-pong prefetch ----
    {
        const int kvg = tid >> 2;   // kv = kvg*4..+3
        const int eq  = tid & 3;    // edges eq*4..+3
        const float* pws = Ws2 + kvg*4;
        const float* pwr = Wr2 + kvg*4;
        u64 att[4][2], arr[4][2];
        #pragma unroll
        for (int kv = 0; kv < 4; kv++) {
            att[kv][0] = att[kv][1] = pk(0.f, 0.f);
            arr[kv][0] = arr[kv][1] = pk(0.f, 0.f);
        }
        float4 wtc[2], wrc[2];
        wtc[0] = *(const float4*)(pws);       wtc[1] = *(const float4*)(pws + WN);
        wrc[0] = *(const float4*)(pwr);       wrc[1] = *(const float4*)(pwr + WN);
        #pragma unroll 2
        for (int i = 0; i < HID; i += 2) {
            float4 wtn[2], wrn[2];
            const int inx = (i + 2 < HID) ? i + 2 : i;
            wtn[0] = *(const float4*)(pws + inx*WN);     wtn[1] = *(const float4*)(pws + (inx+1)*WN);
            wrn[0] = *(const float4*)(pwr + inx*WN);     wrn[1] = *(const float4*)(pwr + (inx+1)*WN);
            #pragma unroll
            for (int j = 0; j < 2; j++) {
                ulonglong2 hh = *(const ulonglong2*)(h1t + (i+j)*20 + eq*4);
                ulonglong2 rr = *(const ulonglong2*)(r1t + (i+j)*20 + eq*4);
                float wts[4] = {wtc[j].x, wtc[j].y, wtc[j].z, wtc[j].w};
                float wrs[4] = {wrc[j].x, wrc[j].y, wrc[j].z, wrc[j].w};
                #pragma unroll
                for (int kv = 0; kv < 4; kv++) {
                    u64 w2 = pk(wts[kv], wts[kv]);
                    fma2(att[kv][0], hh.x, w2);
                    fma2(att[kv][1], hh.y, w2);
                }
                #pragma unroll
                for (int kv = 0; kv < 4; kv++) {
                    u64 w3 = pk(wrs[kv], wrs[kv]);
                    fma2(arr[kv][0], rr.x, w3);
                    fma2(arr[kv][1], rr.y, w3);
                }
            }
            wtc[0] = wtn[0]; wtc[1] = wtn[1];
            wrc[0] = wrn[0]; wrc[1] = wrn[1];
        }
        #pragma unroll
        for (int kv = 0; kv < 4; kv++) {
            float b2 = bs2[kvg*4+kv], c2 = br2[kvg*4+kv];
            #pragma unroll
            for (int p = 0; p < 2; p++) {
                float2 t = up(att[kv][p]), r = up(arr[kv][p]);
                *(u64*)(tpwT + (kvg*4+kv)*20 + eq*4 + p*2) =
                    pk((t.x + b2) * (r.x + c2), (t.y + b2) * (r.y + c2));
            }
        }
    }
    __syncthreads();

    // ---- Phase 4a: out_v gated -> Vt[u][3c x 16e] ----
    for (int idx = tid; idx < TE * TPV; idx += BT) {
        int e = idx & 15, u = idx >> 4;
        float vx, vy, vz;
        if (u < 64) {
            float coef = tpwT[(64+u)*20+e] * spsT[u*16+e];
            vx = coef * vpsT[(192 +       u)*16+e];
            vy = coef * vpsT[(192 + 64  + u)*16+e];
            vz = coef * vpsT[(192 + 128 + u)*16+e];
        } else if (u < 128) {
            int uu = u - 64;
            float coef = tpwT[(128+uu)*20+e] * spsT[(64+uu)*16+e];
            vx = coef * vpsT[(      uu)*16+e];
            vy = coef * vpsT[( 64 + uu)*16+e];
            vz = coef * vpsT[(128 + uu)*16+e];
        } else {
            int uu = u - 128;
            float w5 = tpwT[(256+uu)*20+e] * INV_SQRT2;
            float ax = vpsT[uu*16+e],       ay = vpsT[(64+uu)*16+e],  az = vpsT[(128+uu)*16+e];
            float bx = vpsT[(192+uu)*16+e], by = vpsT[(256+uu)*16+e], bz = vpsT[(320+uu)*16+e];
            vx = w5 * (ay*bz - az*by);
            vy = w5 * (az*bx - ax*bz);
            vz = w5 * (ax*by - ay*bx);
        }
        float nrm = sqrtf(vx*vx + vy*vy + vz*vz + 1e-12f);
        float g = siluf(nrm * gwp[u] + gbp[u]);
        Vt[u*48 +  0 + e] = vx * g;
        Vt[u*48 + 16 + e] = vy * g;
        Vt[u*48 + 32 + e] = vz * g;
    }

    // ---- Phase 4b: out_s -> outsT[j][e] ----
    for (int idx = tid; idx < TE * TPS; idx += BT) {
        int e = idx & 15, j = idx >> 4;
        float val;
        if (j < 64) {
            val = tpwT[j*20+e] * spsT[j*16+e] * spsT[(64+j)*16+e];
        } else {
            int u = j - 64;
            float dt = vpsT[u*16+e]       * vpsT[(192+u)*16+e]
                     + vpsT[(64+u)*16+e]  * vpsT[(256+u)*16+e]
                     + vpsT[(128+u)*16+e] * vpsT[(320+u)*16+e];
            val = tpwT[(192+u)*20+e] * dt * INV_SQRT3;
        }
        outsT[j*16+e] = siluf(val);
    }
    __syncthreads();

    // ---- Phase 5: tid<192 -> fij_v (4v x 4cols); tid>=192 -> fij_s (2v x 4e) ----
    if (tid < 192) {
        const int vg = tid & 15;    // v = vg*4..+3
        const int cg = tid >> 4;    // cols cg*4..+3 of 48
        const float* pw = Wpost_v + vg*4;
        u64 acc[4][2];
        #pragma unroll
        for (int p = 0; p < 4; p++) acc[p][0] = acc[p][1] = pk(0.f, 0.f);
        float4 wc0 = *(const float4*)(pw);
        float4 wc1 = *(const float4*)(pw + NV);
        #pragma unroll 2
        for (int u = 0; u < TPV; u += 2) {
            const int un = (u + 2 < TPV) ? u + 2 : u;
            float4 wn0 = *(const float4*)(pw + un*NV);
            float4 wn1 = *(const float4*)(pw + (un+1)*NV);
            #pragma unroll
            for (int j = 0; j < 2; j++) {
                float4 w = j ? wc1 : wc0;
                ulonglong2 vv = *(const ulonglong2*)(Vt + (u+j)*48 + cg*4);
                float ws[4] = {w.x, w.y, w.z, w.w};
                #pragma unroll
                for (int p = 0; p < 4; p++) {
                    u64 ww = pk(ws[p], ws[p]);
                    fma2(acc[p][0], vv.x, ww);
                    fma2(acc[p][1], vv.y, ww);
                }
            }
            wc0 = wn0; wc1 = wn1;
        }
        const int c  = cg >> 2;            // all 4 cols share c
        const int eb = (cg & 3) * 4;       // edge base
        #pragma unroll
        for (int p = 0; p < 4; p++) {
            int v = vg*4 + p;
            #pragma unroll
            for (int h = 0; h < 2; h++) {
                float2 q = up(acc[p][h]);
                size_t o0 = (size_t)(e0 + eb + h*2)     * 256 + 64 + (size_t)v*3 + c;
                size_t o1 = (size_t)(e0 + eb + h*2 + 1) * 256 + 64 + (size_t)v*3 + c;
                out[o0] = fij_in[o0] + q.x;
                out[o1] = fij_in[o1] + q.y;
            }
        }
    } else {
        const int t  = tid - 192;   // 0..127
        const int vp = t >> 2;      // v = vp*2, vp*2+1
        const int eq = t & 3;       // edges eq*4..+3
        const float* pw = Wpost_s + vp*2;
        u64 a0[2] = {pk(0.f,0.f), pk(0.f,0.f)};
        u64 a1[2] = {pk(0.f,0.f), pk(0.f,0.f)};
        float2 wc[4];
        #pragma unroll
        for (int j = 0; j < 4; j++) wc[j] = *(const float2*)(pw + j*NS);
        for (int i = 0; i < TPS; i += 4) {
            float2 wn[4];
            const int inx = (i + 4 < TPS) ? i + 4 : i;
            #pragma unroll
            for (int j = 0; j < 4; j++) wn[j] = *(const float2*)(pw + (inx+j)*NS);
            #pragma unroll
            for (int j = 0; j < 4; j++) {
                ulonglong2 oo = *(const ulonglong2*)(outsT + (i+j)*16 + eq*4);
                u64 w0 = pk(wc[j].x, wc[j].x), w1 = pk(wc[j].y, wc[j].y);
                fma2(a0[0], oo.x, w0); fma2(a0[1], oo.y, w0);
                fma2(a1[0], oo.x, w1); fma2(a1[1], oo.y, w1);
            }
            #pragma unroll
            for (int j = 0; j < 4; j++) wc[j] = wn[j];
        }
        #pragma unroll
        for (int vv = 0; vv < 2; vv++) {
            #pragma unroll
            for (int h = 0; h < 2; h++) {
                float2 q = up(vv ? a1[h] : a0[h]);
                size_t o0 = (size_t)(e0 + eq*4 + h*2)     * 256 + vp*2 + vv;
                size_t o1 = (size_t)(e0 + eq*4 + h*2 + 1) * 256 + vp*2 + vv;
                out[o0] = fij_in[o0] + q.x;
                out[o1] = fij_in[o1] + q.y;
            }
        }
    }
}

// ---------------------------------------------------------------------------
extern "C" void kernel_launch(void* const* d_in, const int* in_sizes, int n_in,
                              void* d_out, int out_size)
{
    const float* x         = (const float*)d_in[0];
    const float* edge_attr = (const float*)d_in[1];
    const float* fij_in    = (const float*)d_in[2];
    const float* W_pre_s   = (const float*)d_in[3];
    const float* b_pre_s   = (const float*)d_in[4];
    const float* W_pre_v   = (const float*)d_in[5];
    const float* gw_pre    = (const float*)d_in[6];
    const float* gb_pre    = (const float*)d_in[7];
    const float* Ws1       = (const float*)d_in[8];
    const float* bs1       = (const float*)d_in[9];
    const float* Ws2       = (const float*)d_in[10];
    const float* bs2       = (const float*)d_in[11];
    const float* Wr1       = (const float*)d_in[12];
    const float* br1       = (const float*)d_in[13];
    const float* Wr2       = (const float*)d_in[14];
    const float* br2       = (const float*)d_in[15];
    const float* gw_post   = (const float*)d_in[16];
    const float* gb_post   = (const float*)d_in[17];
    const float* W_post_s  = (const float*)d_in[18];
    const float* W_post_v  = (const float*)d_in[19];
    const int*   ei        = (const int*)d_in[20];

    const int N = in_sizes[0] / 256;
    const int E = in_sizes[2] / 256;

    node_kernel<<<(N + 3) / 4, 256>>>(x, W_pre_s, b_pre_s, W_pre_v, gw_pre, gb_pre, N);

    const size_t shm = (size_t)SMEM_FLOATS * 4;   // 104832 B
    cudaFuncSetAttribute(edge_kernel, cudaFuncAttributeMaxDynamicSharedMemorySize, (int)shm);

    edge_kernel<<<E / TE, BT, shm>>>(
        x, edge_attr, fij_in,
        Ws1, bs1, Ws2, bs2, Wr1, br1, Wr2, br2,
        gw_post, gb_post, W_post_s, W_post_v,
        ei, (float*)d_out, E);
}